// round 6
// baseline (speedup 1.0000x reference)
#include <cuda_runtime.h>
#include <math_constants.h>

// Problem constants: B=512, T=512, D=128, H=128
#define BB 512
#define TT 512
#define DD 128
#define HH 128

#define NTHREADS 256
#define NWARPS 8
#define ROWS_PER_WARP (TT / NWARPS)     // 64
#define NBATCH (ROWS_PER_WARP / 4)      // 16 batches of 4 rows
#define STAGES 3                         // per-warp cp.async ring depth
#define STAGE_F4 (4 * 32)                // 4 rows * 32 float4 = 2KB per stage

// ---------------- cp.async helpers ----------------
__device__ __forceinline__ void cp_async16(void* smem_dst, const void* gmem_src) {
    unsigned s = (unsigned)__cvta_generic_to_shared(smem_dst);
    asm volatile("cp.async.cg.shared.global [%0], [%1], 16;\n" :: "r"(s), "l"(gmem_src));
}
__device__ __forceinline__ void cp_commit() {
    asm volatile("cp.async.commit_group;\n");
}
template <int N>
__device__ __forceinline__ void cp_wait() {
    asm volatile("cp.async.wait_group %0;\n" :: "n"(N));
}

__device__ __forceinline__ float blockReduceSum(float v, float* sred) {
    #pragma unroll
    for (int o = 16; o; o >>= 1) v += __shfl_xor_sync(0xffffffffu, v, o);
    int warp = threadIdx.x >> 5, lane = threadIdx.x & 31;
    if (lane == 0) sred[warp] = v;
    __syncthreads();
    if (warp == 0) {
        float x = (lane < NWARPS) ? sred[lane] : 0.0f;
        #pragma unroll
        for (int o = 4; o; o >>= 1) x += __shfl_xor_sync(0xffffffffu, x, o);
        if (lane == 0) sred[0] = x;
    }
    __syncthreads();
    float r = sred[0];
    __syncthreads();
    return r;
}

__device__ __forceinline__ int blockReduceSumInt(int v, int* sred) {
    #pragma unroll
    for (int o = 16; o; o >>= 1) v += __shfl_xor_sync(0xffffffffu, v, o);
    int warp = threadIdx.x >> 5, lane = threadIdx.x & 31;
    if (lane == 0) sred[warp] = v;
    __syncthreads();
    if (warp == 0) {
        int x = (lane < NWARPS) ? sred[lane] : 0;
        #pragma unroll
        for (int o = 4; o; o >>= 1) x += __shfl_xor_sync(0xffffffffu, x, o);
        if (lane == 0) sred[0] = x;
    }
    __syncthreads();
    int r = sred[0];
    __syncthreads();
    return r;
}

__global__ __launch_bounds__(NTHREADS, 4)
void single_attention_kernel(const float* __restrict__ input,   // [B,T,D]
                             const int*   __restrict__ mask,    // [B,T]
                             const float* __restrict__ Wt,      // [D,H]
                             const float* __restrict__ Wx,      // [D,H]
                             const float* __restrict__ rate,    // [1]
                             float* __restrict__ out_v,         // [B,D] or null
                             float* __restrict__ out_a)         // [B,T] or null
{
    // per-warp cp.async ring: [NWARPS][STAGES][4 rows][32 float4] = 48 KB
    extern __shared__ float4 s_ring[];

    __shared__ float s_w[TT];                // unnormalized weights exp(e)
    __shared__ int   s_m[TT];
    __shared__ float s_q[HH], s_lv[DD], s_r[DD];
    __shared__ float s_qp[2][HH];
    __shared__ float s_rp[2][DD];
    __shared__ float s_redf[NWARPS];
    __shared__ int   s_redi[NWARPS];

    const int b    = blockIdx.x;
    const int tid  = threadIdx.x;
    const int warp = tid >> 5, lane = tid & 31;

    const float* __restrict__ gx = input + (size_t)b * TT * DD;
    const int*   __restrict__ mb = mask  + (size_t)b * TT;

    const int tw0 = warp * ROWS_PER_WARP;
    const float4* __restrict__ grow = (const float4*)gx + (size_t)tw0 * (DD / 4);
    float4* __restrict__ myring = s_ring + warp * (STAGES * STAGE_F4);

    // ---- kick off first 2 batches into the ring immediately ----
    #pragma unroll
    for (int j = 0; j < 2; j++) {
        float4* slot = myring + (j % STAGES) * STAGE_F4;
        #pragma unroll
        for (int r = 0; r < 4; r++)
            cp_async16(slot + r * 32 + lane, grow + (size_t)(j * 4 + r) * 32 + lane);
        cp_commit();
    }

    // ---------------- prologue: mask, last_visit, q, r ----------------
    int m0 = mb[tid], m1 = mb[tid + 256];
    s_m[tid] = m0; s_m[tid + 256] = m1;
    int msum = blockReduceSumInt(m0 + m1, s_redi);
    int last = msum - 1; if (last < 0) last = 0;

    if (tid < DD) s_lv[tid] = gx[(size_t)last * DD + tid];
    __syncthreads();

    // q[h] = sum_d lv[d] * Wt[d,h]  (2-way d-chunk)
    {
        int c = tid >> 7, h = tid & 127;
        float acc = 0.0f;
        #pragma unroll 8
        for (int d = c * 64; d < c * 64 + 64; d++)
            acc += s_lv[d] * Wt[d * HH + h];
        s_qp[c][h] = acc;
    }
    __syncthreads();
    if (tid < HH) s_q[tid] = s_qp[0][tid] + s_qp[1][tid];
    __syncthreads();

    // r[d] = sum_h Wx[d,h] * q[h]  (2-way h-chunk, float4)
    {
        int c = tid >> 7, d = tid & 127;
        const float4* wrow = (const float4*)(Wx + (size_t)d * HH) + c * 16;
        const float4* qv   = (const float4*)s_q + c * 16;
        float acc = 0.0f;
        #pragma unroll
        for (int j = 0; j < 16; j++) {
            float4 w = wrow[j], qq = qv[j];
            acc += w.x * qq.x + w.y * qq.y + w.z * qq.z + w.w * qq.w;
        }
        s_rp[c][d] = acc;
    }
    __syncthreads();
    if (tid < DD) s_r[tid] = s_rp[0][tid] + s_rp[1][tid];
    __syncthreads();

    const float srate = __fdividef(1.0f, 1.0f + __expf(-rate[0]));
    const float4 rr = ((const float4*)s_r)[lane];
    const int myrow = ((lane >> 4) & 1) + (((lane >> 3) & 1) << 1);

    float4 acc0 = make_float4(0.f, 0.f, 0.f, 0.f);
    float4 acc1 = make_float4(0.f, 0.f, 0.f, 0.f);

    // ---------------- main loop: per-warp ring, no barriers ----------------
    #pragma unroll 4
    for (int i = 0; i < NBATCH; i++) {
        // issue batch i+2 into its ring slot; commit EVERY iteration so
        // wait_group<2> below always means "batch i is complete".
        const int nb = i + 2;
        if (nb < NBATCH) {
            float4* slot = myring + (nb % STAGES) * STAGE_F4;
            #pragma unroll
            for (int r = 0; r < 4; r++)
                cp_async16(slot + r * 32 + lane, grow + (size_t)(nb * 4 + r) * 32 + lane);
        }
        cp_commit();
        cp_wait<2>();          // batch i resident (same-thread data: no barrier needed)

        const float4* slot = myring + (i % STAGES) * STAGE_F4;
        const float4 cur0 = slot[0 * 32 + lane];
        const float4 cur1 = slot[1 * 32 + lane];
        const float4 cur2 = slot[2 * 32 + lane];
        const float4 cur3 = slot[3 * 32 + lane];

        float p0 = cur0.x * rr.x + cur0.y * rr.y + cur0.z * rr.z + cur0.w * rr.w;
        float p1 = cur1.x * rr.x + cur1.y * rr.y + cur1.z * rr.z + cur1.w * rr.w;
        float p2 = cur2.x * rr.x + cur2.y * rr.y + cur2.z * rr.z + cur2.w * rr.w;
        float p3 = cur3.x * rr.x + cur3.y * rr.y + cur3.z * rr.z + cur3.w * rr.w;

        // 9-shfl combined reduce: 8-lane group owns one row
        p0 += __shfl_xor_sync(0xffffffffu, p0, 16);
        p1 += __shfl_xor_sync(0xffffffffu, p1, 16);
        float v01 = (lane & 16) ? p1 : p0;
        p2 += __shfl_xor_sync(0xffffffffu, p2, 16);
        p3 += __shfl_xor_sync(0xffffffffu, p3, 16);
        float v23 = (lane & 16) ? p3 : p2;
        v01 += __shfl_xor_sync(0xffffffffu, v01, 8);
        v23 += __shfl_xor_sync(0xffffffffu, v23, 8);
        float v = (lane & 8) ? v23 : v01;
        v += __shfl_xor_sync(0xffffffffu, v, 4);
        v += __shfl_xor_sync(0xffffffffu, v, 2);
        v += __shfl_xor_sync(0xffffffffu, v, 1);

        // weight math (fast transcendentals), once per 4 rows
        const int t = tw0 + 4 * i + myrow;
        float sig   = __fdividef(1.0f, 1.0f + __expf(-v));
        float denom = srate * (__logf(2.72f + (1.0f - sig)) * (float)(TT - t));
        float e     = fmaxf(__fdividef(sig, denom), 0.0f);
        float w     = (s_m[t] != 0) ? __expf(e) : 0.0f;

        if ((lane & 7) == 0) s_w[t] = w;     // lanes 0,8,16,24 -> rows 0,2,1,3
        float w0 = __shfl_sync(0xffffffffu, w, 0);
        float w1 = __shfl_sync(0xffffffffu, w, 16);
        float w2 = __shfl_sync(0xffffffffu, w, 8);
        float w3 = __shfl_sync(0xffffffffu, w, 24);

        acc0.x += w0 * cur0.x + w1 * cur1.x;
        acc0.y += w0 * cur0.y + w1 * cur1.y;
        acc0.z += w0 * cur0.z + w1 * cur1.z;
        acc0.w += w0 * cur0.w + w1 * cur1.w;
        acc1.x += w2 * cur2.x + w3 * cur3.x;
        acc1.y += w2 * cur2.y + w3 * cur3.y;
        acc1.z += w2 * cur2.z + w3 * cur3.z;
        acc1.w += w2 * cur2.w + w3 * cur3.w;
    }

    acc0.x += acc1.x; acc0.y += acc1.y; acc0.z += acc1.z; acc0.w += acc1.w;

    // ---------------- epilogue (ring reused as v-reduction buffer) ----------------
    cp_wait<0>();                 // this warp's outstanding groups drained
    __syncthreads();              // ALL warps done reading rings before reuse (R5 bug fix)
    float4* s_vred = s_ring;      // [NWARPS][32 float4] — overlays warp 0's ring, now safe
    s_vred[warp * 32 + lane] = acc0;
    __syncthreads();              // publish s_w and s_vred

    float part = s_w[tid] + s_w[tid + 256];
    float l = blockReduceSum(part, s_redf);
    float inv = __fdividef(1.0f, l);

    if (out_a) {
        out_a[(size_t)b * TT + tid]       = s_w[tid] * inv;
        out_a[(size_t)b * TT + 256 + tid] = s_w[tid + 256] * inv;
    }

    if (out_v && tid < 32) {
        float4 v = make_float4(0.f, 0.f, 0.f, 0.f);
        #pragma unroll
        for (int g = 0; g < NWARPS; g++) {
            float4 c = s_vred[g * 32 + tid];
            v.x += c.x; v.y += c.y; v.z += c.z; v.w += c.w;
        }
        v.x *= inv; v.y *= inv; v.z *= inv; v.w *= inv;
        ((float4*)(out_v + (size_t)b * DD))[tid] = v;
    }
}

extern "C" void kernel_launch(void* const* d_in, const int* in_sizes, int n_in,
                              void* d_out, int out_size) {
    const float* input = (const float*)d_in[0];
    const int*   mask  = (const int*)  d_in[1];
    const float* Wt    = (const float*)d_in[2];
    const float* Wx    = (const float*)d_in[3];
    const float* rate  = (const float*)d_in[4];

    float* out = (float*)d_out;
    float* out_v = nullptr;
    float* out_a = nullptr;

    if (out_size == BB * DD + BB * TT) {        // (v, a) concatenated
        out_v = out;
        out_a = out + BB * DD;
    } else if (out_size == BB * DD) {           // v only
        out_v = out;
    } else {                                    // a only
        out_a = out;
    }

    static int smem_set = 0;
    const int dyn_smem = NWARPS * STAGES * STAGE_F4 * sizeof(float4);   // 48 KB
    if (!smem_set) {
        cudaFuncSetAttribute(single_attention_kernel,
                             cudaFuncAttributeMaxDynamicSharedMemorySize, dyn_smem);
        smem_set = 1;
    }

    single_attention_kernel<<<BB, NTHREADS, dyn_smem>>>(
        input, mask, Wt, Wx, rate, out_v, out_a);
}